// round 13
// baseline (speedup 1.0000x reference)
#include <cuda_runtime.h>
#include <cuda_fp16.h>
#include <cstdint>
#include <math.h>

// ---------------- problem constants ----------------
#define BATCH   16384
#define M4      65536
#define M12     196608
#define EPS     1e-5f
#define NCHUNK  256
#define GY4     1024

#define APADH 40
#define BPADH 264

// ---------------- PTX helpers (plain sm_80+ PTX only) ----------------
__device__ __forceinline__ void cp16(uint32_t dst, const void* src) {
    asm volatile("cp.async.cg.shared.global [%0], [%1], 16;" :: "r"(dst), "l"(src));
}
__device__ __forceinline__ uint32_t smem_u32(const void* p) {
    uint32_t a;
    asm("{ .reg .u64 t; cvta.to.shared.u64 t, %1; cvt.u32.u64 %0, t; }" : "=r"(a) : "l"(p));
    return a;
}
__device__ __forceinline__ void mma16816(float* c, const uint32_t* a, const uint32_t* b) {
    asm volatile(
        "mma.sync.aligned.m16n8k16.row.col.f32.f16.f16.f32 "
        "{%0,%1,%2,%3},{%4,%5,%6,%7},{%8,%9},{%0,%1,%2,%3};"
        : "+f"(c[0]), "+f"(c[1]), "+f"(c[2]), "+f"(c[3])
        : "r"(a[0]), "r"(a[1]), "r"(a[2]), "r"(a[3]), "r"(b[0]), "r"(b[1]));
}
__device__ __forceinline__ void ldmx4(uint32_t* r, uint32_t addr) {
    asm volatile("ldmatrix.sync.aligned.m8n8.x4.shared.b16 {%0,%1,%2,%3}, [%4];"
        : "=r"(r[0]), "=r"(r[1]), "=r"(r[2]), "=r"(r[3]) : "r"(addr));
}
__device__ __forceinline__ void ldmx4t(uint32_t* r, uint32_t addr) {
    asm volatile("ldmatrix.sync.aligned.m8n8.x4.trans.shared.b16 {%0,%1,%2,%3}, [%4];"
        : "=r"(r[0]), "=r"(r[1]), "=r"(r[2]), "=r"(r[3]) : "r"(addr));
}

// ---------------- static scratch ----------------
__device__ __half g_xh    [(size_t)M4  * 256];
__device__ __half g_XNH   [(size_t)M4  * 512];
__device__ __half g_XNODE [(size_t)M4  * 256];
__device__ __half g_P     [(size_t)M4  * 512];
__device__ __half g_Q     [(size_t)M4  * 512];
__device__ __half g_XMSG  [(size_t)M12 * 256];
__device__ __half g_XAGG  [(size_t)M4  * 256];
__device__ __half g_FH    [(size_t)M4  * 512];

__device__ float  g_part  [2 * NCHUNK * 512];
__device__ float  g_part2 [2 * GY4 * 512];
__device__ float  g_bpart [7 * 8 * 512];
__device__ float  g_sbuf  [7 * 512];
__device__ float  g_tbuf  [7 * 512];
__device__ float  g_zero  [512];

__device__ __half g_Whn0 [256 * 512];
__device__ __half g_Whn1 [512 * 256];
__device__ __half g_Whp  [256 * 512];
__device__ __half g_Whq  [256 * 512];
__device__ __half g_Whm1 [512 * 256];
__device__ __half g_Whf0 [512 * 512];
__device__ __half g_Whf1 [512 * 256];

// ---------------- small kernels ----------------
__global__ void cvt_colstats(const float* __restrict__ x, __half* __restrict__ xh,
                             float* __restrict__ part)
{
    int c = threadIdx.x;   // 256
    float sm = 0.f, ss = 0.f;
    for (int r = blockIdx.x; r < M4; r += NCHUNK) {
        __half h = __float2half(x[(size_t)r * 256 + c]);
        xh[(size_t)r * 256 + c] = h;
        float v = __half2float(h);
        sm += v; ss += v * v;
    }
    part[(size_t)blockIdx.x * 256 + c]            = sm;
    part[(size_t)(NCHUNK + blockIdx.x) * 256 + c] = ss;
}

__global__ void nk_final_fold3(const float* __restrict__ part, int M,
    const float* g0, const float* b0, float* s0, float* t0,
    const float* g1, const float* b1, float* s1, float* t1,
    const float* g2, const float* b2, float* s2, float* t2)
{
    int c = threadIdx.x;  // 256
    float sm = 0.f, ss = 0.f;
    for (int i = 0; i < NCHUNK; ++i) {
        sm += part[(size_t)i * 256 + c];
        ss += part[(size_t)(NCHUNK + i) * 256 + c];
    }
    float m = sm / (float)M;
    float r = rsqrtf(ss / (float)M - m * m + EPS);
    { float sc = g0[c] * r; s0[c] = sc; t0[c] = b0[c] - m * sc; }
    { float sc = g1[c] * r; s1[c] = sc; t1[c] = b1[c] - m * sc; }
    { float sc = g2[c] * r; s2[c] = sc; t2[c] = b2[c] - m * sc; }
}

__global__ void nk_final_fold(const float* __restrict__ part, int stride, int coloff, int M,
    const float* __restrict__ g, const float* __restrict__ b,
    float* __restrict__ s, float* __restrict__ t)
{
    int c = threadIdx.x;
    float sm = 0.f, ss = 0.f;
    for (int i = 0; i < NCHUNK; ++i) {
        sm += part[(size_t)i * stride + coloff + c];
        ss += part[(size_t)(NCHUNK + i) * stride + coloff + c];
    }
    float m = sm / (float)M;
    float r = rsqrtf(ss / (float)M - m * m + EPS);
    float sc = g[c] * r;
    s[c] = sc;
    t[c] = b[c] - m * sc;
}

__global__ void cta_final_fold(const float* __restrict__ part2, int M,
    const float* __restrict__ g, const float* __restrict__ b,
    float* __restrict__ s, float* __restrict__ t)
{
    int c = threadIdx.x;
    float sm = 0.f, ss = 0.f;
    for (int i = 0; i < GY4; ++i) {
        sm += part2[(size_t)i * 512 + c];
        ss += part2[(size_t)(GY4 + i) * 512 + c];
    }
    float m = sm / (float)M;
    float r = rsqrtf(ss / (float)M - m * m + EPS);
    float sc = g[c] * r;
    s[c] = sc;
    t[c] = b[c] - m * sc;
}

__global__ void pqstats_partial(const __half* __restrict__ P, const __half* __restrict__ Q,
                                float* __restrict__ part)
{
    int c = threadIdx.x;  // 512
    float sm = 0.f, ss = 0.f;
    for (int b = blockIdx.x; b < BATCH; b += gridDim.x) {
        float pv[4], qv[4];
        #pragma unroll
        for (int i = 0; i < 4; ++i) {
            pv[i] = __half2float(P[((size_t)b * 4 + i) * 512 + c]);
            qv[i] = __half2float(Q[((size_t)b * 4 + i) * 512 + c]);
        }
        #pragma unroll
        for (int i = 0; i < 4; ++i)
            #pragma unroll
            for (int j = 0; j < 4; ++j)
                if (i != j) {
                    float v = fmaxf(pv[i] + qv[j], 0.f);
                    sm += v; ss += v * v;
                }
    }
    part[(size_t)blockIdx.x * 512 + c]            = sm;
    part[(size_t)(NCHUNK + blockIdx.x) * 512 + c] = ss;
}

__global__ void fold_wb(const float* __restrict__ W, const float* __restrict__ s,
                        const float* __restrict__ t,
                        __half* __restrict__ Wh, float* __restrict__ bp, int K, int N)
{
    int n  = blockIdx.x * 128 + threadIdx.x;
    int kg = blockIdx.y;
    int kn = K >> 3;
    int k0 = kg * kn;
    float a = 0.f;
    for (int k = k0; k < k0 + kn; ++k) {
        float w = W[(size_t)k * N + n];
        Wh[(size_t)k * N + n] = __float2half(w * s[k]);
        a += t[k] * w;
    }
    bp[kg * 512 + n] = a;
}

__global__ void avg3_stats(const __half* __restrict__ XMSG, __half* __restrict__ XAGG,
                           float* __restrict__ part)
{
    int c = threadIdx.x;   // 256
    const float inv3 = 1.f / 3.f;
    float sm = 0.f, ss = 0.f;
    for (int bi = blockIdx.x; bi < M4; bi += NCHUNK) {
        size_t base = (size_t)bi * 3 * 256 + c;
        float a = __half2float(XMSG[base]);
        float b = __half2float(XMSG[base + 256]);
        float d = __half2float(XMSG[base + 512]);
        __half h = __float2half((a + b + d) * inv3);
        XAGG[(size_t)bi * 256 + c] = h;
        float v = __half2float(h);
        sm += v; ss += v * v;
    }
    part[(size_t)blockIdx.x * 512 + 256 + c]            = sm;
    part[(size_t)(NCHUNK + blockIdx.x) * 512 + 256 + c] = ss;
}

// ---------------- fp16 mma GEMM -----------------------------------------------
// CTA: 256 threads (8 warps: wm 2 x wn 4), tile 64x256, warp tile 32x64, 4-stage.
// Mainloop loads BOTH k16 steps' fragments before issuing the 32 HMMAs.
#define NSTAGE 4
#define A_ST  (64 * APADH)
#define B_ST  (32 * BPADH)
#define SHM_BYTES ((NSTAGE * (A_ST + B_ST)) * 2)

template<int AMODE>
__device__ __forceinline__ void stageA(uint32_t uAbuf, __half* smAbuf,
                                       const __half* __restrict__ A,
                                       const __half* __restrict__ A2,
                                       int row0, int kbase, int K, int tid)
{
    int row = tid >> 2;
    int c8  = tid & 3;
    int gk  = kbase + c8 * 8;
    if (AMODE != 1) {
        const __half* src;
        if (AMODE == 0) src = &A[(size_t)(row0 + row) * K + gk];
        else src = (gk < 256) ? &A [(size_t)(row0 + row) * 256 + gk]
                              : &A2[(size_t)(row0 + row) * 256 + gk - 256];
        cp16(uAbuf + (uint32_t)(row * APADH + c8 * 8) * 2u, src);
    } else {
        const __half2 z2 = __float2half2_rn(0.f);
        int gr  = row0 + row;
        int b   = gr / 12;
        int rem = gr - b * 12;
        int i   = rem / 3;
        int jj  = rem - i * 3;
        int j   = jj + (jj >= i);
        uint4 pv4 = *reinterpret_cast<const uint4*>(&A [((size_t)b * 4 + i) * 512 + gk]);
        uint4 qv4 = *reinterpret_cast<const uint4*>(&A2[((size_t)b * 4 + j) * 512 + gk]);
        const __half2* ph = reinterpret_cast<const __half2*>(&pv4);
        const __half2* qh = reinterpret_cast<const __half2*>(&qv4);
        __half2 o[4];
        #pragma unroll
        for (int q = 0; q < 4; ++q)
            o[q] = __hmax2(__hadd2(ph[q], qh[q]), z2);
        *reinterpret_cast<uint4*>(&smAbuf[row * APADH + c8 * 8]) =
            *reinterpret_cast<uint4*>(o);
    }
}

__device__ __forceinline__ void stageB(uint32_t uBbuf, const __half* __restrict__ Wh,
                                       int colblk, int kbase, int N, int tid)
{
    #pragma unroll
    for (int p = 0; p < 4; ++p) {
        int lin = p * 256 + tid;
        int k   = lin >> 5;
        int c8  = lin & 31;
        cp16(uBbuf + (uint32_t)(k * BPADH + c8 * 8) * 2u,
             &Wh[(size_t)(kbase + k) * N + colblk + c8 * 8]);
    }
}

template<int AMODE, int EPI, int OTYPE, int STAT>
__global__ void __launch_bounds__(256, 2)
gemm_h(const __half* __restrict__ A, const __half* __restrict__ A2,
       const __half* __restrict__ Wh,
       const float* __restrict__ cvec, const float* __restrict__ bp,
       void* __restrict__ Cout, float* __restrict__ part2, int K, int N)
{
    extern __shared__ __half sm[];
    __half* smA = sm;
    __half* smB = sm + NSTAGE * A_ST;
    const uint32_t uA = smem_u32(smA);
    const uint32_t uB = smem_u32(smB);

    const int tid    = threadIdx.x;
    const int lane   = tid & 31;
    const int warp   = tid >> 5;
    const int wm     = warp >> 2;
    const int wn     = warp & 3;
    const int row0   = blockIdx.y * 64;
    const int colblk = blockIdx.x * 256;

    float acc[2][8][4];
    #pragma unroll
    for (int a = 0; a < 2; ++a)
        #pragma unroll
        for (int b = 0; b < 8; ++b)
            #pragma unroll
            for (int q = 0; q < 4; ++q) acc[a][b][q] = 0.f;

    const int NC = K >> 5;
    #pragma unroll
    for (int s = 0; s < 3; ++s) {
        stageA<AMODE>(uA + (uint32_t)(s * A_ST) * 2u, smA + s * A_ST, A, A2, row0, s * 32, K, tid);
        stageB(uB + (uint32_t)(s * B_ST) * 2u, Wh, colblk, s * 32, N, tid);
        asm volatile("cp.async.commit_group;");
    }

    const int aLrow = ((lane >> 3) & 1) * 8 + (lane & 7);
    const int aLcol = (lane >> 4) * 8;
    const int lm    = lane >> 3;
    const int lrow  = (lane & 7) + (lm & 1) * 8;
    const int lcol  = (lm >> 1) * 8;

    for (int c = 0; c < NC; ++c) {
        asm volatile("cp.async.wait_group 2;");
        __syncthreads();
        if (c + 3 < NC) {
            int s = (c + 3) & (NSTAGE - 1);
            stageA<AMODE>(uA + (uint32_t)(s * A_ST) * 2u, smA + s * A_ST, A, A2, row0, (c + 3) * 32, K, tid);
            stageB(uB + (uint32_t)(s * B_ST) * 2u, Wh, colblk, (c + 3) * 32, N, tid);
        }
        asm volatile("cp.async.commit_group;");

        const int sb = c & (NSTAGE - 1);
        const uint32_t cA = uA + (uint32_t)(sb * A_ST) * 2u;
        const uint32_t cB = uB + (uint32_t)(sb * B_ST) * 2u;

        // ---- load ALL fragments for both k16 steps first (max scoreboard distance)
        uint32_t af[2][2][4];     // [step][mt][reg]
        uint32_t bf[2][8][2];     // [step][nt][reg]
        #pragma unroll
        for (int s = 0; s < 2; ++s) {
            const int kloc = s * 16;
            #pragma unroll
            for (int mt = 0; mt < 2; ++mt) {
                uint32_t addr = cA + (uint32_t)((wm * 32 + mt * 16 + aLrow) * APADH + kloc + aLcol) * 2u;
                ldmx4(af[s][mt], addr);
            }
            #pragma unroll
            for (int ntt = 0; ntt < 4; ++ntt) {
                uint32_t r[4];
                uint32_t addr = cB + (uint32_t)((kloc + lrow) * BPADH
                                 + wn * 64 + ntt * 16 + lcol) * 2u;
                ldmx4t(r, addr);
                bf[s][ntt * 2][0]     = r[0];
                bf[s][ntt * 2][1]     = r[1];
                bf[s][ntt * 2 + 1][0] = r[2];
                bf[s][ntt * 2 + 1][1] = r[3];
            }
        }
        // ---- then 32 HMMAs back-to-back
        #pragma unroll
        for (int s = 0; s < 2; ++s)
            #pragma unroll
            for (int mt = 0; mt < 2; ++mt)
                #pragma unroll
                for (int nt = 0; nt < 8; ++nt)
                    mma16816(acc[mt][nt], af[s][mt], bf[s][nt]);
    }

    // ---- cooperative folded-bias compute
    __syncthreads();
    float* smBias = (float*)sm;
    {
        int col = colblk + tid;
        float a = cvec[col];
        #pragma unroll
        for (int kg = 0; kg < 8; ++kg) a += bp[kg * 512 + col];
        smBias[tid] = a;
    }
    __syncthreads();

    float cs[8][2], cq[8][2];
    if (STAT) {
        #pragma unroll
        for (int nt = 0; nt < 8; ++nt) { cs[nt][0]=cs[nt][1]=cq[nt][0]=cq[nt][1]=0.f; }
    }
    #pragma unroll
    for (int mt = 0; mt < 2; ++mt) {
        int r0 = row0 + wm * 32 + mt * 16 + (lane >> 2);
        #pragma unroll
        for (int nt = 0; nt < 8; ++nt) {
            int cloc = wn * 64 + nt * 8 + (lane & 3) * 2;
            int col  = colblk + cloc;
            float b0 = smBias[cloc], b1 = smBias[cloc + 1];
            float v0 = acc[mt][nt][0] + b0;
            float v1 = acc[mt][nt][1] + b1;
            float v2 = acc[mt][nt][2] + b0;
            float v3 = acc[mt][nt][3] + b1;
            if (EPI == 1) {
                v0 = fmaxf(v0, 0.f); v1 = fmaxf(v1, 0.f);
                v2 = fmaxf(v2, 0.f); v3 = fmaxf(v3, 0.f);
            } else if (EPI == 2) {
                v0 = 1.f / (1.f + __expf(-v0));
                v1 = 1.f / (1.f + __expf(-v1));
                v2 = 1.f / (1.f + __expf(-v2));
                v3 = 1.f / (1.f + __expf(-v3));
            }
            if (STAT) {
                cs[nt][0] += v0 + v2;           cs[nt][1] += v1 + v3;
                cq[nt][0] += v0 * v0 + v2 * v2; cq[nt][1] += v1 * v1 + v3 * v3;
            }
            if (OTYPE == 0) {
                __half* C = (__half*)Cout;
                *reinterpret_cast<__half2*>(&C[(size_t)r0 * N + col])       = __floats2half2_rn(v0, v1);
                *reinterpret_cast<__half2*>(&C[(size_t)(r0 + 8) * N + col]) = __floats2half2_rn(v2, v3);
            } else {
                float* C = (float*)Cout;
                *reinterpret_cast<float2*>(&C[(size_t)r0 * N + col])       = make_float2(v0, v1);
                *reinterpret_cast<float2*>(&C[(size_t)(r0 + 8) * N + col]) = make_float2(v2, v3);
            }
        }
    }
    if (STAT) {
        #pragma unroll
        for (int nt = 0; nt < 8; ++nt)
            #pragma unroll
            for (int p = 0; p < 2; ++p) {
                #pragma unroll
                for (int off = 4; off < 32; off <<= 1) {
                    cs[nt][p] += __shfl_xor_sync(0xFFFFFFFF, cs[nt][p], off);
                    cq[nt][p] += __shfl_xor_sync(0xFFFFFFFF, cq[nt][p], off);
                }
            }
        float* smStat = (float*)sm + 256;
        if (wm == 1 && (lane >> 2) == 0) {
            #pragma unroll
            for (int nt = 0; nt < 8; ++nt) {
                int cloc = wn * 64 + nt * 8 + (lane & 3) * 2;
                smStat[cloc]           = cs[nt][0];
                smStat[cloc + 1]       = cs[nt][1];
                smStat[256 + cloc]     = cq[nt][0];
                smStat[256 + cloc + 1] = cq[nt][1];
            }
        }
        __syncthreads();
        if (wm == 0 && (lane >> 2) == 0) {
            #pragma unroll
            for (int nt = 0; nt < 8; ++nt) {
                int cloc = wn * 64 + nt * 8 + (lane & 3) * 2;
                int col  = colblk + cloc;
                part2[(size_t)blockIdx.y * 512 + col]             = cs[nt][0] + smStat[cloc];
                part2[(size_t)blockIdx.y * 512 + col + 1]         = cs[nt][1] + smStat[cloc + 1];
                part2[(size_t)(GY4 + blockIdx.y) * 512 + col]     = cq[nt][0] + smStat[256 + cloc];
                part2[(size_t)(GY4 + blockIdx.y) * 512 + col + 1] = cq[nt][1] + smStat[256 + cloc + 1];
            }
        }
    }
}

// ---------------- launch ----------------
template<typename Tp>
static inline Tp* sym(const void* symbol)
{
    void* p = nullptr;
    cudaGetSymbolAddress(&p, symbol);
    return (Tp*)p;
}

extern "C" void kernel_launch(void* const* d_in, const int* in_sizes, int n_in,
                              void* d_out, int out_size)
{
    const float* x   = (const float*)d_in[0];
    const float* ng0 = (const float*)d_in[1];
    const float* nb0 = (const float*)d_in[2];
    const float* nW0 = (const float*)d_in[3];
    const float* nc0 = (const float*)d_in[4];
    const float* ng1 = (const float*)d_in[5];
    const float* nb1 = (const float*)d_in[6];
    const float* nW1 = (const float*)d_in[7];
    const float* nc1 = (const float*)d_in[8];
    const float* mg0 = (const float*)d_in[9];
    const float* mb0 = (const float*)d_in[10];
    const float* mW0 = (const float*)d_in[11];
    const float* mc0 = (const float*)d_in[12];
    const float* mg1 = (const float*)d_in[13];
    const float* mb1 = (const float*)d_in[14];
    const float* mW1 = (const float*)d_in[15];
    const float* mc1 = (const float*)d_in[16];
    const float* fg0 = (const float*)d_in[17];
    const float* fb0 = (const float*)d_in[18];
    const float* fW0 = (const float*)d_in[19];
    const float* fc0 = (const float*)d_in[20];
    const float* fg1 = (const float*)d_in[21];
    const float* fb1 = (const float*)d_in[22];
    const float* fW1 = (const float*)d_in[23];
    const float* fc1 = (const float*)d_in[24];
    float* out = (float*)d_out;

    __half* xh    = sym<__half>(g_xh);
    __half* XNH   = sym<__half>(g_XNH);
    __half* XNODE = sym<__half>(g_XNODE);
    __half* P     = sym<__half>(g_P);
    __half* Q     = sym<__half>(g_Q);
    __half* XMSG  = sym<__half>(g_XMSG);
    __half* XAGG  = sym<__half>(g_XAGG);
    __half* FH    = sym<__half>(g_FH);
    float*  part  = sym<float >(g_part);
    float*  part2 = sym<float >(g_part2);
    float*  bpart = sym<float >(g_bpart);
    float*  S     = sym<float >(g_sbuf);
    float*  T     = sym<float >(g_tbuf);
    float*  zero  = sym<float >(g_zero);

    __half* Whn0 = sym<__half>(g_Whn0);
    __half* Whn1 = sym<__half>(g_Whn1);
    __half* Whp  = sym<__half>(g_Whp);
    __half* Whq  = sym<__half>(g_Whq);
    __half* Whm1 = sym<__half>(g_Whm1);
    __half* Whf0 = sym<__half>(g_Whf0);
    __half* Whf1 = sym<__half>(g_Whf1);

    float* bp_n0 = bpart + 0 * 8 * 512;
    float* bp_n1 = bpart + 1 * 8 * 512;
    float* bp_p  = bpart + 2 * 8 * 512;
    float* bp_q  = bpart + 3 * 8 * 512;
    float* bp_m1 = bpart + 4 * 8 * 512;
    float* bp_f0 = bpart + 5 * 8 * 512;
    float* bp_f1 = bpart + 6 * 8 * 512;

    float *s_n0 = S + 0*512, *t_n0 = T + 0*512;
    float *s_n1 = S + 1*512, *t_n1 = T + 1*512;
    float *s_p  = S + 2*512, *t_p  = T + 2*512;
    float *s_q  = S + 3*512, *t_q  = T + 3*512;
    float *s_m1 = S + 4*512, *t_m1 = T + 4*512;
    float *s_f0 = S + 5*512, *t_f0 = T + 5*512;
    float *s_f1 = S + 6*512, *t_f1 = T + 6*512;

    static cudaStream_t sN = nullptr;
    static cudaEvent_t  eF0 = nullptr, eNode = nullptr;
    if (!sN) {
        cudaStreamCreateWithFlags(&sN, cudaStreamNonBlocking);
        cudaEventCreateWithFlags(&eF0,   cudaEventDisableTiming);
        cudaEventCreateWithFlags(&eNode, cudaEventDisableTiming);
        cudaFuncSetAttribute(gemm_h<0,1,0,1>, cudaFuncAttributeMaxDynamicSharedMemorySize, SHM_BYTES);
        cudaFuncSetAttribute(gemm_h<0,2,0,1>, cudaFuncAttributeMaxDynamicSharedMemorySize, SHM_BYTES);
        cudaFuncSetAttribute(gemm_h<0,0,0,0>, cudaFuncAttributeMaxDynamicSharedMemorySize, SHM_BYTES);
        cudaFuncSetAttribute(gemm_h<1,2,0,0>, cudaFuncAttributeMaxDynamicSharedMemorySize, SHM_BYTES);
        cudaFuncSetAttribute(gemm_h<2,1,0,1>, cudaFuncAttributeMaxDynamicSharedMemorySize, SHM_BYTES);
        cudaFuncSetAttribute(gemm_h<0,2,1,0>, cudaFuncAttributeMaxDynamicSharedMemorySize, SHM_BYTES);
    }

    // ---- shared prologue (stream 0)
    cvt_colstats<<<NCHUNK, 256>>>(x, xh, part);
    nk_final_fold3<<<1, 256>>>(part, M4,
        ng0, nb0, s_n0, t_n0,
        mg0, mb0, s_p,  t_p,
        mg0 + 256, mb0 + 256, s_q, t_q);
    cudaEventRecord(eF0, 0);
    cudaStreamWaitEvent(sN, eF0, 0);

    // ---- node branch (stream sN)
    fold_wb<<<dim3(4, 8), 128, 0, sN>>>(nW0, s_n0, t_n0, Whn0, bp_n0, 256, 512);
    gemm_h<0,1,0,1><<<dim3(2, GY4), 256, SHM_BYTES, sN>>>(xh, nullptr, Whn0, nc0, bp_n0, XNH, part2, 256, 512);
    cta_final_fold<<<1, 512, 0, sN>>>(part2, M4, ng1, nb1, s_n1, t_n1);
    fold_wb<<<dim3(2, 8), 128, 0, sN>>>(nW1, s_n1, t_n1, Whn1, bp_n1, 512, 256);
    gemm_h<0,2,0,1><<<dim3(1, GY4), 256, SHM_BYTES, sN>>>(XNH, nullptr, Whn1, nc1, bp_n1, XNODE, part2, 512, 256);
    cta_final_fold<<<1, 256, 0, sN>>>(part2, M4, fg0, fb0, s_f0, t_f0);
    cudaEventRecord(eNode, sN);

    // ---- msg branch (stream 0)
    fold_wb<<<dim3(4, 8), 128>>>(mW0,             s_p, t_p, Whp, bp_p, 256, 512);
    fold_wb<<<dim3(4, 8), 128>>>(mW0 + 256 * 512, s_q, t_q, Whq, bp_q, 256, 512);
    gemm_h<0,0,0,0><<<dim3(2, GY4), 256, SHM_BYTES>>>(xh, nullptr, Whp, zero, bp_p, P, nullptr, 256, 512);
    gemm_h<0,0,0,0><<<dim3(2, GY4), 256, SHM_BYTES>>>(xh, nullptr, Whq, mc0,  bp_q, Q, nullptr, 256, 512);
    pqstats_partial<<<NCHUNK, 512>>>(P, Q, part);
    nk_final_fold<<<1, 512>>>(part, 512, 0, M12, mg1, mb1, s_m1, t_m1);
    fold_wb<<<dim3(2, 8), 128>>>(mW1, s_m1, t_m1, Whm1, bp_m1, 512, 256);
    gemm_h<1,2,0,0><<<dim3(1, M12/64), 256, SHM_BYTES>>>(P, Q, Whm1, mc1, bp_m1, XMSG, nullptr, 512, 256);
    avg3_stats<<<NCHUNK, 256>>>(XMSG, XAGG, part);
    nk_final_fold<<<1, 256>>>(part, 512, 256, M4, fg0 + 256, fb0 + 256, s_f0 + 256, t_f0 + 256);

    // ---- join + final MLP (stream 0)
    cudaStreamWaitEvent(0, eNode, 0);
    fold_wb<<<dim3(4, 8), 128>>>(fW0, s_f0, t_f0, Whf0, bp_f0, 512, 512);
    gemm_h<2,1,0,1><<<dim3(2, GY4), 256, SHM_BYTES>>>(XNODE, XAGG, Whf0, fc0, bp_f0, FH, part2, 512, 512);
    cta_final_fold<<<1, 512>>>(part2, M4, fg1, fb1, s_f1, t_f1);
    fold_wb<<<dim3(2, 8), 128>>>(fW1, s_f1, t_f1, Whf1, bp_f1, 512, 256);
    gemm_h<0,2,1,0><<<dim3(1, GY4), 256, SHM_BYTES>>>(FH, nullptr, Whf1, fc1, bp_f1, out, nullptr, 512, 256);
}

// round 14
// speedup vs baseline: 1.0882x; 1.0882x over previous
#include <cuda_runtime.h>
#include <cuda_fp16.h>
#include <cstdint>
#include <math.h>

// ---------------- problem constants ----------------
#define BATCH   16384
#define M4      65536
#define M12     196608
#define EPS     1e-5f
#define NCHUNK  256
#define GY4     1024

#define APADH 72    // A smem row stride in halves (64-k + 8)
#define BPADH 264   // B smem row stride in halves (256-n + 8)

// ---------------- PTX helpers (plain sm_80+ PTX only) ----------------
__device__ __forceinline__ void cp16(uint32_t dst, const void* src) {
    asm volatile("cp.async.cg.shared.global [%0], [%1], 16;" :: "r"(dst), "l"(src));
}
__device__ __forceinline__ uint32_t smem_u32(const void* p) {
    uint32_t a;
    asm("{ .reg .u64 t; cvta.to.shared.u64 t, %1; cvt.u32.u64 %0, t; }" : "=r"(a) : "l"(p));
    return a;
}
__device__ __forceinline__ void mma16816(float* c, const uint32_t* a, const uint32_t* b) {
    asm volatile(
        "mma.sync.aligned.m16n8k16.row.col.f32.f16.f16.f32 "
        "{%0,%1,%2,%3},{%4,%5,%6,%7},{%8,%9},{%0,%1,%2,%3};"
        : "+f"(c[0]), "+f"(c[1]), "+f"(c[2]), "+f"(c[3])
        : "r"(a[0]), "r"(a[1]), "r"(a[2]), "r"(a[3]), "r"(b[0]), "r"(b[1]));
}
__device__ __forceinline__ void ldmx4(uint32_t* r, uint32_t addr) {
    asm volatile("ldmatrix.sync.aligned.m8n8.x4.shared.b16 {%0,%1,%2,%3}, [%4];"
        : "=r"(r[0]), "=r"(r[1]), "=r"(r[2]), "=r"(r[3]) : "r"(addr));
}
__device__ __forceinline__ void ldmx4t(uint32_t* r, uint32_t addr) {
    asm volatile("ldmatrix.sync.aligned.m8n8.x4.trans.shared.b16 {%0,%1,%2,%3}, [%4];"
        : "=r"(r[0]), "=r"(r[1]), "=r"(r[2]), "=r"(r[3]) : "r"(addr));
}

// ---------------- static scratch ----------------
__device__ __half g_xh    [(size_t)M4  * 256];
__device__ __half g_XNH   [(size_t)M4  * 512];
__device__ __half g_XNODE [(size_t)M4  * 256];
__device__ __half g_P     [(size_t)M4  * 512];
__device__ __half g_Q     [(size_t)M4  * 512];
__device__ __half g_XMSG  [(size_t)M12 * 256];
__device__ __half g_XAGG  [(size_t)M4  * 256];
__device__ __half g_FH    [(size_t)M4  * 512];

__device__ float  g_part  [2 * NCHUNK * 512];
__device__ float  g_part2 [2 * GY4 * 512];
__device__ float  g_bpart [7 * 8 * 512];
__device__ float  g_sbuf  [7 * 512];
__device__ float  g_tbuf  [7 * 512];
__device__ float  g_zero  [512];

__device__ __half g_Whn0 [256 * 512];
__device__ __half g_Whn1 [512 * 256];
__device__ __half g_Whp  [256 * 512];
__device__ __half g_Whq  [256 * 512];
__device__ __half g_Whm1 [512 * 256];
__device__ __half g_Whf0 [512 * 512];
__device__ __half g_Whf1 [512 * 256];

// ---------------- small kernels ----------------
__global__ void cvt_colstats(const float* __restrict__ x, __half* __restrict__ xh,
                             float* __restrict__ part)
{
    int c = threadIdx.x;   // 256
    float sm = 0.f, ss = 0.f;
    for (int r = blockIdx.x; r < M4; r += NCHUNK) {
        __half h = __float2half(x[(size_t)r * 256 + c]);
        xh[(size_t)r * 256 + c] = h;
        float v = __half2float(h);
        sm += v; ss += v * v;
    }
    part[(size_t)blockIdx.x * 256 + c]            = sm;
    part[(size_t)(NCHUNK + blockIdx.x) * 256 + c] = ss;
}

__global__ void nk_final_fold3(const float* __restrict__ part, int M,
    const float* g0, const float* b0, float* s0, float* t0,
    const float* g1, const float* b1, float* s1, float* t1,
    const float* g2, const float* b2, float* s2, float* t2)
{
    int c = threadIdx.x;  // 256
    float sm = 0.f, ss = 0.f;
    for (int i = 0; i < NCHUNK; ++i) {
        sm += part[(size_t)i * 256 + c];
        ss += part[(size_t)(NCHUNK + i) * 256 + c];
    }
    float m = sm / (float)M;
    float r = rsqrtf(ss / (float)M - m * m + EPS);
    { float sc = g0[c] * r; s0[c] = sc; t0[c] = b0[c] - m * sc; }
    { float sc = g1[c] * r; s1[c] = sc; t1[c] = b1[c] - m * sc; }
    { float sc = g2[c] * r; s2[c] = sc; t2[c] = b2[c] - m * sc; }
}

__global__ void nk_final_fold(const float* __restrict__ part, int stride, int coloff, int M,
    const float* __restrict__ g, const float* __restrict__ b,
    float* __restrict__ s, float* __restrict__ t)
{
    int c = threadIdx.x;
    float sm = 0.f, ss = 0.f;
    for (int i = 0; i < NCHUNK; ++i) {
        sm += part[(size_t)i * stride + coloff + c];
        ss += part[(size_t)(NCHUNK + i) * stride + coloff + c];
    }
    float m = sm / (float)M;
    float r = rsqrtf(ss / (float)M - m * m + EPS);
    float sc = g[c] * r;
    s[c] = sc;
    t[c] = b[c] - m * sc;
}

__global__ void cta_final_fold(const float* __restrict__ part2, int M,
    const float* __restrict__ g, const float* __restrict__ b,
    float* __restrict__ s, float* __restrict__ t)
{
    int c = threadIdx.x;
    float sm = 0.f, ss = 0.f;
    for (int i = 0; i < GY4; ++i) {
        sm += part2[(size_t)i * 512 + c];
        ss += part2[(size_t)(GY4 + i) * 512 + c];
    }
    float m = sm / (float)M;
    float r = rsqrtf(ss / (float)M - m * m + EPS);
    float sc = g[c] * r;
    s[c] = sc;
    t[c] = b[c] - m * sc;
}

__global__ void pqstats_partial(const __half* __restrict__ P, const __half* __restrict__ Q,
                                float* __restrict__ part)
{
    int c = threadIdx.x;  // 512
    float sm = 0.f, ss = 0.f;
    for (int b = blockIdx.x; b < BATCH; b += gridDim.x) {
        float pv[4], qv[4];
        #pragma unroll
        for (int i = 0; i < 4; ++i) {
            pv[i] = __half2float(P[((size_t)b * 4 + i) * 512 + c]);
            qv[i] = __half2float(Q[((size_t)b * 4 + i) * 512 + c]);
        }
        #pragma unroll
        for (int i = 0; i < 4; ++i)
            #pragma unroll
            for (int j = 0; j < 4; ++j)
                if (i != j) {
                    float v = fmaxf(pv[i] + qv[j], 0.f);
                    sm += v; ss += v * v;
                }
    }
    part[(size_t)blockIdx.x * 512 + c]            = sm;
    part[(size_t)(NCHUNK + blockIdx.x) * 512 + c] = ss;
}

__global__ void fold_wb(const float* __restrict__ W, const float* __restrict__ s,
                        const float* __restrict__ t,
                        __half* __restrict__ Wh, float* __restrict__ bp, int K, int N)
{
    int n  = blockIdx.x * 128 + threadIdx.x;
    int kg = blockIdx.y;
    int kn = K >> 3;
    int k0 = kg * kn;
    float a = 0.f;
    for (int k = k0; k < k0 + kn; ++k) {
        float w = W[(size_t)k * N + n];
        Wh[(size_t)k * N + n] = __float2half(w * s[k]);
        a += t[k] * w;
    }
    bp[kg * 512 + n] = a;
}

__global__ void avg3_stats(const __half* __restrict__ XMSG, __half* __restrict__ XAGG,
                           float* __restrict__ part)
{
    int c = threadIdx.x;   // 256
    const float inv3 = 1.f / 3.f;
    float sm = 0.f, ss = 0.f;
    for (int bi = blockIdx.x; bi < M4; bi += NCHUNK) {
        size_t base = (size_t)bi * 3 * 256 + c;
        float a = __half2float(XMSG[base]);
        float b = __half2float(XMSG[base + 256]);
        float d = __half2float(XMSG[base + 512]);
        __half h = __float2half((a + b + d) * inv3);
        XAGG[(size_t)bi * 256 + c] = h;
        float v = __half2float(h);
        sm += v; ss += v * v;
    }
    part[(size_t)blockIdx.x * 512 + 256 + c]            = sm;
    part[(size_t)(NCHUNK + blockIdx.x) * 512 + 256 + c] = ss;
}

// ---------------- fp16 mma GEMM -----------------------------------------------
// CTA: 256 threads (8 warps: wm 2 x wn 4), tile 64x256, warp tile 32x64,
// K-chunks of 64, 2-stage double buffer (one __syncthreads per chunk).
#define NSTAGE 2
#define A_ST  (64 * APADH)
#define B_ST  (64 * BPADH)
#define SHM_BYTES ((NSTAGE * (A_ST + B_ST)) * 2)

template<int AMODE>
__device__ __forceinline__ void stageA(uint32_t uAbuf, __half* smAbuf,
                                       const __half* __restrict__ A,
                                       const __half* __restrict__ A2,
                                       int row0, int kbase, int K, int tid)
{
    // 64 rows x 8 c8-chunks = 512 -> 2 per thread
    #pragma unroll
    for (int p = 0; p < 2; ++p) {
        int lin = p * 256 + tid;
        int row = lin >> 3;
        int c8  = lin & 7;
        int gk  = kbase + c8 * 8;
        if (AMODE != 1) {
            const __half* src;
            if (AMODE == 0) src = &A[(size_t)(row0 + row) * K + gk];
            else src = (gk < 256) ? &A [(size_t)(row0 + row) * 256 + gk]
                                  : &A2[(size_t)(row0 + row) * 256 + gk - 256];
            cp16(uAbuf + (uint32_t)(row * APADH + c8 * 8) * 2u, src);
        } else {
            const __half2 z2 = __float2half2_rn(0.f);
            int gr  = row0 + row;
            int b   = gr / 12;
            int rem = gr - b * 12;
            int i   = rem / 3;
            int jj  = rem - i * 3;
            int j   = jj + (jj >= i);
            uint4 pv4 = *reinterpret_cast<const uint4*>(&A [((size_t)b * 4 + i) * 512 + gk]);
            uint4 qv4 = *reinterpret_cast<const uint4*>(&A2[((size_t)b * 4 + j) * 512 + gk]);
            const __half2* ph = reinterpret_cast<const __half2*>(&pv4);
            const __half2* qh = reinterpret_cast<const __half2*>(&qv4);
            __half2 o[4];
            #pragma unroll
            for (int q = 0; q < 4; ++q)
                o[q] = __hmax2(__hadd2(ph[q], qh[q]), z2);
            *reinterpret_cast<uint4*>(&smAbuf[row * APADH + c8 * 8]) =
                *reinterpret_cast<uint4*>(o);
        }
    }
}

__device__ __forceinline__ void stageB(uint32_t uBbuf, const __half* __restrict__ Wh,
                                       int colblk, int kbase, int N, int tid)
{
    #pragma unroll
    for (int p = 0; p < 8; ++p) {
        int lin = p * 256 + tid;
        int k   = lin >> 5;          // 0..63
        int c8  = lin & 31;
        cp16(uBbuf + (uint32_t)(k * BPADH + c8 * 8) * 2u,
             &Wh[(size_t)(kbase + k) * N + colblk + c8 * 8]);
    }
}

template<int AMODE, int EPI, int OTYPE, int STAT>
__global__ void __launch_bounds__(256, 2)
gemm_h(const __half* __restrict__ A, const __half* __restrict__ A2,
       const __half* __restrict__ Wh,
       const float* __restrict__ cvec, const float* __restrict__ bp,
       void* __restrict__ Cout, float* __restrict__ part2, int K, int N)
{
    extern __shared__ __half sm[];
    __half* smA = sm;
    __half* smB = sm + NSTAGE * A_ST;
    const uint32_t uA = smem_u32(smA);
    const uint32_t uB = smem_u32(smB);

    const int tid    = threadIdx.x;
    const int lane   = tid & 31;
    const int warp   = tid >> 5;
    const int wm     = warp >> 2;
    const int wn     = warp & 3;
    const int row0   = blockIdx.y * 64;
    const int colblk = blockIdx.x * 256;

    float acc[2][8][4];
    #pragma unroll
    for (int a = 0; a < 2; ++a)
        #pragma unroll
        for (int b = 0; b < 8; ++b)
            #pragma unroll
            for (int q = 0; q < 4; ++q) acc[a][b][q] = 0.f;

    const int NC = K >> 6;     // 64-wide chunks
    stageA<AMODE>(uA, smA, A, A2, row0, 0, K, tid);
    stageB(uB, Wh, colblk, 0, N, tid);
    asm volatile("cp.async.commit_group;");

    const int aLrow = ((lane >> 3) & 1) * 8 + (lane & 7);
    const int aLcol = (lane >> 4) * 8;
    const int lm    = lane >> 3;
    const int lrow  = (lane & 7) + (lm & 1) * 8;
    const int lcol  = (lm >> 1) * 8;

    for (int c = 0; c < NC; ++c) {
        asm volatile("cp.async.wait_group 0;");
        __syncthreads();
        if (c + 1 < NC) {
            int s = (c + 1) & 1;
            stageA<AMODE>(uA + (uint32_t)(s * A_ST) * 2u, smA + s * A_ST, A, A2, row0, (c + 1) * 64, K, tid);
            stageB(uB + (uint32_t)(s * B_ST) * 2u, Wh, colblk, (c + 1) * 64, N, tid);
            asm volatile("cp.async.commit_group;");
        }

        const int sb = c & 1;
        const uint32_t cA = uA + (uint32_t)(sb * A_ST) * 2u;
        const uint32_t cB = uB + (uint32_t)(sb * B_ST) * 2u;

        #pragma unroll
        for (int s = 0; s < 4; ++s) {          // 4 x k16 per 64-chunk
            const int kloc = s * 16;
            uint32_t af[2][4];
            #pragma unroll
            for (int mt = 0; mt < 2; ++mt) {
                uint32_t addr = cA + (uint32_t)((wm * 32 + mt * 16 + aLrow) * APADH + kloc + aLcol) * 2u;
                ldmx4(af[mt], addr);
            }
            uint32_t bf[8][2];
            #pragma unroll
            for (int ntt = 0; ntt < 4; ++ntt) {
                uint32_t r[4];
                uint32_t addr = cB + (uint32_t)((kloc + lrow) * BPADH
                                 + wn * 64 + ntt * 16 + lcol) * 2u;
                ldmx4t(r, addr);
                bf[ntt * 2][0]     = r[0];
                bf[ntt * 2][1]     = r[1];
                bf[ntt * 2 + 1][0] = r[2];
                bf[ntt * 2 + 1][1] = r[3];
            }
            #pragma unroll
            for (int mt = 0; mt < 2; ++mt)
                #pragma unroll
                for (int nt = 0; nt < 8; ++nt)
                    mma16816(acc[mt][nt], af[mt], bf[nt]);
        }
    }

    // ---- cooperative folded-bias compute
    __syncthreads();
    float* smBias = (float*)sm;
    {
        int col = colblk + tid;
        float a = cvec[col];
        #pragma unroll
        for (int kg = 0; kg < 8; ++kg) a += bp[kg * 512 + col];
        smBias[tid] = a;
    }
    __syncthreads();

    float cs[8][2], cq[8][2];
    if (STAT) {
        #pragma unroll
        for (int nt = 0; nt < 8; ++nt) { cs[nt][0]=cs[nt][1]=cq[nt][0]=cq[nt][1]=0.f; }
    }
    #pragma unroll
    for (int mt = 0; mt < 2; ++mt) {
        int r0 = row0 + wm * 32 + mt * 16 + (lane >> 2);
        #pragma unroll
        for (int nt = 0; nt < 8; ++nt) {
            int cloc = wn * 64 + nt * 8 + (lane & 3) * 2;
            int col  = colblk + cloc;
            float b0 = smBias[cloc], b1 = smBias[cloc + 1];
            float v0 = acc[mt][nt][0] + b0;
            float v1 = acc[mt][nt][1] + b1;
            float v2 = acc[mt][nt][2] + b0;
            float v3 = acc[mt][nt][3] + b1;
            if (EPI == 1) {
                v0 = fmaxf(v0, 0.f); v1 = fmaxf(v1, 0.f);
                v2 = fmaxf(v2, 0.f); v3 = fmaxf(v3, 0.f);
            } else if (EPI == 2) {
                v0 = 1.f / (1.f + __expf(-v0));
                v1 = 1.f / (1.f + __expf(-v1));
                v2 = 1.f / (1.f + __expf(-v2));
                v3 = 1.f / (1.f + __expf(-v3));
            }
            if (STAT) {
                cs[nt][0] += v0 + v2;           cs[nt][1] += v1 + v3;
                cq[nt][0] += v0 * v0 + v2 * v2; cq[nt][1] += v1 * v1 + v3 * v3;
            }
            if (OTYPE == 0) {
                __half* C = (__half*)Cout;
                *reinterpret_cast<__half2*>(&C[(size_t)r0 * N + col])       = __floats2half2_rn(v0, v1);
                *reinterpret_cast<__half2*>(&C[(size_t)(r0 + 8) * N + col]) = __floats2half2_rn(v2, v3);
            } else {
                float* C = (float*)Cout;
                *reinterpret_cast<float2*>(&C[(size_t)r0 * N + col])       = make_float2(v0, v1);
                *reinterpret_cast<float2*>(&C[(size_t)(r0 + 8) * N + col]) = make_float2(v2, v3);
            }
        }
    }
    if (STAT) {
        #pragma unroll
        for (int nt = 0; nt < 8; ++nt)
            #pragma unroll
            for (int p = 0; p < 2; ++p) {
                #pragma unroll
                for (int off = 4; off < 32; off <<= 1) {
                    cs[nt][p] += __shfl_xor_sync(0xFFFFFFFF, cs[nt][p], off);
                    cq[nt][p] += __shfl_xor_sync(0xFFFFFFFF, cq[nt][p], off);
                }
            }
        float* smStat = (float*)sm + 256;
        if (wm == 1 && (lane >> 2) == 0) {
            #pragma unroll
            for (int nt = 0; nt < 8; ++nt) {
                int cloc = wn * 64 + nt * 8 + (lane & 3) * 2;
                smStat[cloc]           = cs[nt][0];
                smStat[cloc + 1]       = cs[nt][1];
                smStat[256 + cloc]     = cq[nt][0];
                smStat[256 + cloc + 1] = cq[nt][1];
            }
        }
        __syncthreads();
        if (wm == 0 && (lane >> 2) == 0) {
            #pragma unroll
            for (int nt = 0; nt < 8; ++nt) {
                int cloc = wn * 64 + nt * 8 + (lane & 3) * 2;
                int col  = colblk + cloc;
                part2[(size_t)blockIdx.y * 512 + col]             = cs[nt][0] + smStat[cloc];
                part2[(size_t)blockIdx.y * 512 + col + 1]         = cs[nt][1] + smStat[cloc + 1];
                part2[(size_t)(GY4 + blockIdx.y) * 512 + col]     = cq[nt][0] + smStat[256 + cloc];
                part2[(size_t)(GY4 + blockIdx.y) * 512 + col + 1] = cq[nt][1] + smStat[256 + cloc + 1];
            }
        }
    }
}

// ---------------- launch ----------------
template<typename Tp>
static inline Tp* sym(const void* symbol)
{
    void* p = nullptr;
    cudaGetSymbolAddress(&p, symbol);
    return (Tp*)p;
}

extern "C" void kernel_launch(void* const* d_in, const int* in_sizes, int n_in,
                              void* d_out, int out_size)
{
    const float* x   = (const float*)d_in[0];
    const float* ng0 = (const float*)d_in[1];
    const float* nb0 = (const float*)d_in[2];
    const float* nW0 = (const float*)d_in[3];
    const float* nc0 = (const float*)d_in[4];
    const float* ng1 = (const float*)d_in[5];
    const float* nb1 = (const float*)d_in[6];
    const float* nW1 = (const float*)d_in[7];
    const float* nc1 = (const float*)d_in[8];
    const float* mg0 = (const float*)d_in[9];
    const float* mb0 = (const float*)d_in[10];
    const float* mW0 = (const float*)d_in[11];
    const float* mc0 = (const float*)d_in[12];
    const float* mg1 = (const float*)d_in[13];
    const float* mb1 = (const float*)d_in[14];
    const float* mW1 = (const float*)d_in[15];
    const float* mc1 = (const float*)d_in[16];
    const float* fg0 = (const float*)d_in[17];
    const float* fb0 = (const float*)d_in[18];
    const float* fW0 = (const float*)d_in[19];
    const float* fc0 = (const float*)d_in[20];
    const float* fg1 = (const float*)d_in[21];
    const float* fb1 = (const float*)d_in[22];
    const float* fW1 = (const float*)d_in[23];
    const float* fc1 = (const float*)d_in[24];
    float* out = (float*)d_out;

    __half* xh    = sym<__half>(g_xh);
    __half* XNH   = sym<__half>(g_XNH);
    __half* XNODE = sym<__half>(g_XNODE);
    __half* P     = sym<__half>(g_P);
    __half* Q     = sym<__half>(g_Q);
    __half* XMSG  = sym<__half>(g_XMSG);
    __half* XAGG  = sym<__half>(g_XAGG);
    __half* FH    = sym<__half>(g_FH);
    float*  part  = sym<float >(g_part);
    float*  part2 = sym<float >(g_part2);
    float*  bpart = sym<float >(g_bpart);
    float*  S     = sym<float >(g_sbuf);
    float*  T     = sym<float >(g_tbuf);
    float*  zero  = sym<float >(g_zero);

    __half* Whn0 = sym<__half>(g_Whn0);
    __half* Whn1 = sym<__half>(g_Whn1);
    __half* Whp  = sym<__half>(g_Whp);
    __half* Whq  = sym<__half>(g_Whq);
    __half* Whm1 = sym<__half>(g_Whm1);
    __half* Whf0 = sym<__half>(g_Whf0);
    __half* Whf1 = sym<__half>(g_Whf1);

    float* bp_n0 = bpart + 0 * 8 * 512;
    float* bp_n1 = bpart + 1 * 8 * 512;
    float* bp_p  = bpart + 2 * 8 * 512;
    float* bp_q  = bpart + 3 * 8 * 512;
    float* bp_m1 = bpart + 4 * 8 * 512;
    float* bp_f0 = bpart + 5 * 8 * 512;
    float* bp_f1 = bpart + 6 * 8 * 512;

    float *s_n0 = S + 0*512, *t_n0 = T + 0*512;
    float *s_n1 = S + 1*512, *t_n1 = T + 1*512;
    float *s_p  = S + 2*512, *t_p  = T + 2*512;
    float *s_q  = S + 3*512, *t_q  = T + 3*512;
    float *s_m1 = S + 4*512, *t_m1 = T + 4*512;
    float *s_f0 = S + 5*512, *t_f0 = T + 5*512;
    float *s_f1 = S + 6*512, *t_f1 = T + 6*512;

    static cudaStream_t sN = nullptr;
    static cudaEvent_t  eF0 = nullptr, eNode = nullptr;
    if (!sN) {
        cudaStreamCreateWithFlags(&sN, cudaStreamNonBlocking);
        cudaEventCreateWithFlags(&eF0,   cudaEventDisableTiming);
        cudaEventCreateWithFlags(&eNode, cudaEventDisableTiming);
        cudaFuncSetAttribute(gemm_h<0,1,0,1>, cudaFuncAttributeMaxDynamicSharedMemorySize, SHM_BYTES);
        cudaFuncSetAttribute(gemm_h<0,2,0,1>, cudaFuncAttributeMaxDynamicSharedMemorySize, SHM_BYTES);
        cudaFuncSetAttribute(gemm_h<0,0,0,0>, cudaFuncAttributeMaxDynamicSharedMemorySize, SHM_BYTES);
        cudaFuncSetAttribute(gemm_h<1,2,0,0>, cudaFuncAttributeMaxDynamicSharedMemorySize, SHM_BYTES);
        cudaFuncSetAttribute(gemm_h<2,1,0,1>, cudaFuncAttributeMaxDynamicSharedMemorySize, SHM_BYTES);
        cudaFuncSetAttribute(gemm_h<0,2,1,0>, cudaFuncAttributeMaxDynamicSharedMemorySize, SHM_BYTES);
    }

    // ---- shared prologue (stream 0)
    cvt_colstats<<<NCHUNK, 256>>>(x, xh, part);
    nk_final_fold3<<<1, 256>>>(part, M4,
        ng0, nb0, s_n0, t_n0,
        mg0, mb0, s_p,  t_p,
        mg0 + 256, mb0 + 256, s_q, t_q);
    cudaEventRecord(eF0, 0);
    cudaStreamWaitEvent(sN, eF0, 0);

    // ---- node branch (stream sN)
    fold_wb<<<dim3(4, 8), 128, 0, sN>>>(nW0, s_n0, t_n0, Whn0, bp_n0, 256, 512);
    gemm_h<0,1,0,1><<<dim3(2, GY4), 256, SHM_BYTES, sN>>>(xh, nullptr, Whn0, nc0, bp_n0, XNH, part2, 256, 512);
    cta_final_fold<<<1, 512, 0, sN>>>(part2, M4, ng1, nb1, s_n1, t_n1);
    fold_wb<<<dim3(2, 8), 128, 0, sN>>>(nW1, s_n1, t_n1, Whn1, bp_n1, 512, 256);
    gemm_h<0,2,0,1><<<dim3(1, GY4), 256, SHM_BYTES, sN>>>(XNH, nullptr, Whn1, nc1, bp_n1, XNODE, part2, 512, 256);
    cta_final_fold<<<1, 256, 0, sN>>>(part2, M4, fg0, fb0, s_f0, t_f0);
    cudaEventRecord(eNode, sN);

    // ---- msg branch (stream 0)
    fold_wb<<<dim3(4, 8), 128>>>(mW0,             s_p, t_p, Whp, bp_p, 256, 512);
    fold_wb<<<dim3(4, 8), 128>>>(mW0 + 256 * 512, s_q, t_q, Whq, bp_q, 256, 512);
    gemm_h<0,0,0,0><<<dim3(2, GY4), 256, SHM_BYTES>>>(xh, nullptr, Whp, zero, bp_p, P, nullptr, 256, 512);
    gemm_h<0,0,0,0><<<dim3(2, GY4), 256, SHM_BYTES>>>(xh, nullptr, Whq, mc0,  bp_q, Q, nullptr, 256, 512);
    pqstats_partial<<<NCHUNK, 512>>>(P, Q, part);
    nk_final_fold<<<1, 512>>>(part, 512, 0, M12, mg1, mb1, s_m1, t_m1);
    fold_wb<<<dim3(2, 8), 128>>>(mW1, s_m1, t_m1, Whm1, bp_m1, 512, 256);
    gemm_h<1,2,0,0><<<dim3(1, M12/64), 256, SHM_BYTES>>>(P, Q, Whm1, mc1, bp_m1, XMSG, nullptr, 512, 256);
    avg3_stats<<<NCHUNK, 256>>>(XMSG, XAGG, part);
    nk_final_fold<<<1, 256>>>(part, 512, 256, M4, fg0 + 256, fb0 + 256, s_f0 + 256, t_f0 + 256);

    // ---- join + final MLP (stream 0)
    cudaStreamWaitEvent(0, eNode, 0);
    fold_wb<<<dim3(4, 8), 128>>>(fW0, s_f0, t_f0, Whf0, bp_f0, 512, 512);
    gemm_h<2,1,0,1><<<dim3(2, GY4), 256, SHM_BYTES>>>(XNODE, XAGG, Whf0, fc0, bp_f0, FH, part2, 512, 512);
    cta_final_fold<<<1, 512>>>(part2, M4, fg1, fb1, s_f1, t_f1);
    fold_wb<<<dim3(2, 8), 128>>>(fW1, s_f1, t_f1, Whf1, bp_f1, 512, 256);
    gemm_h<0,2,1,0><<<dim3(1, GY4), 256, SHM_BYTES>>>(FH, nullptr, Whf1, fc1, bp_f1, out, nullptr, 512, 256);
}